// round 5
// baseline (speedup 1.0000x reference)
#include <cuda_runtime.h>
#include <cstdint>

#define MAXN 50000
#define MAXE 800000
#define NHEADS 4
#define FDIM 128
#define NEG_SLOPE 0.2f
#define GAT_EPS 1e-16f

#define SCAN_T 1024
#define SCAN_C 52            // ints per scan thread; SCAN_T*SCAN_C = 53248 >= MAXN
#define DEG_PAD (SCAN_T * SCAN_C)

// ---------------- scratch (static device globals; no allocation) ----------------
__device__ float g_h[(size_t)MAXN * FDIM];            // 25.6 MB: h = x @ W^T
__device__ float g_asrc[MAXN * NHEADS];               // per-node src logits
__device__ float g_adst[MAXN * NHEADS];               // per-node dst logits
__device__ int   g_deg[DEG_PAD];                      // per-dst degree (padded)
__device__ int   g_off[MAXN + 1];                     // CSR offsets
__device__ int   g_cur[MAXN];                         // scatter cursors
__device__ unsigned long long g_sedge[MAXE];          // packed (eid<<32 | src), dst-sorted
__device__ float g_exs[(size_t)MAXE * NHEADS];        // exp(alpha), dst-sorted order
__device__ int   g_idx64;                             // 1 if edge_index is int64

// ---------------- helpers ----------------
__device__ __forceinline__ unsigned f2tf(float x) {
    unsigned u;
    asm("cvt.rna.tf32.f32 %0, %1;" : "=r"(u) : "f"(x));
    return u;
}
__device__ __forceinline__ float lrelu_exp(float v) {
    float a = v > 0.0f ? v : v * NEG_SLOPE;
    return __expf(a);
}
__device__ __forceinline__ void load_edge(const void* ei, int e, int E, int& src, int& dst) {
    if (g_idx64) {
        const long long* p = (const long long*)ei;
        src = (int)p[e];
        dst = (int)p[(size_t)E + e];
    } else {
        const int* p = (const int*)ei;
        src = p[e];
        dst = p[(size_t)E + e];
    }
}

// ---------------- zero degree counters + dtype detect (fused) ----------------
__global__ void k_init(const unsigned* __restrict__ w) {
    int i = blockIdx.x * blockDim.x + threadIdx.x;
    if (i < DEG_PAD) g_deg[i] = 0;
    if (i == 0) {
        int is64 = 1;
        #pragma unroll 8
        for (int k = 1; k < 256; k += 2) {
            if (w[k] != 0u) { is64 = 0; break; }
        }
        g_idx64 = is64;
    }
}

// ---------------- tf32 tensor-core GEMM + fused attention logits ----------------
#define SMST 136
__global__ __launch_bounds__(256) void k_gemm_att(const float* __restrict__ x,
                                                  const float* __restrict__ W,
                                                  const float* __restrict__ att_src,
                                                  const float* __restrict__ att_dst,
                                                  int n) {
    __shared__ float xs[32][SMST];   // xs[k][m]
    __shared__ float ws[32][SMST];   // ws[k][o]

    int tid = threadIdx.x;
    int lane = tid & 31, warp = tid >> 5;
    int gid = lane >> 2, tig = lane & 3;
    int mw = warp & 3, nw = warp >> 2;
    int mbase = mw * 32, nbase = nw * 64;
    int row0 = blockIdx.x * 128;

    float acc[2][8][4];
    #pragma unroll
    for (int mf = 0; mf < 2; mf++)
        #pragma unroll
        for (int nf = 0; nf < 8; nf++)
            #pragma unroll
            for (int r = 0; r < 4; r++) acc[mf][nf][r] = 0.0f;

    for (int kk = 0; kk < FDIM; kk += 32) {
        #pragma unroll
        for (int it = 0; it < 4; it++) {
            int v = tid + it * 256;
            int m = v & 127, kq = v >> 7;
            int gr = row0 + m;
            float4 xv = make_float4(0.f, 0.f, 0.f, 0.f);
            if (gr < n) xv = *(const float4*)&x[(size_t)gr * FDIM + kk + kq * 4];
            xs[kq * 4 + 0][m] = xv.x;
            xs[kq * 4 + 1][m] = xv.y;
            xs[kq * 4 + 2][m] = xv.z;
            xs[kq * 4 + 3][m] = xv.w;
            float4 wv = *(const float4*)&W[(size_t)m * FDIM + kk + kq * 4];
            ws[kq * 4 + 0][m] = wv.x;
            ws[kq * 4 + 1][m] = wv.y;
            ws[kq * 4 + 2][m] = wv.z;
            ws[kq * 4 + 3][m] = wv.w;
        }
        __syncthreads();

        #pragma unroll
        for (int ks = 0; ks < 4; ks++) {
            int k0 = ks * 8;
            unsigned a[2][4];
            #pragma unroll
            for (int mf = 0; mf < 2; mf++) {
                int r = mbase + mf * 16 + gid;
                a[mf][0] = f2tf(xs[k0 + tig][r]);
                a[mf][1] = f2tf(xs[k0 + tig][r + 8]);
                a[mf][2] = f2tf(xs[k0 + tig + 4][r]);
                a[mf][3] = f2tf(xs[k0 + tig + 4][r + 8]);
            }
            #pragma unroll
            for (int nf = 0; nf < 8; nf++) {
                int c = nbase + nf * 8 + gid;
                unsigned b0 = f2tf(ws[k0 + tig][c]);
                unsigned b1 = f2tf(ws[k0 + tig + 4][c]);
                #pragma unroll
                for (int mf = 0; mf < 2; mf++) {
                    asm volatile(
                        "mma.sync.aligned.m16n8k8.row.col.f32.tf32.tf32.f32 "
                        "{%0,%1,%2,%3}, {%4,%5,%6,%7}, {%8,%9}, {%0,%1,%2,%3};"
                        : "+f"(acc[mf][nf][0]), "+f"(acc[mf][nf][1]),
                          "+f"(acc[mf][nf][2]), "+f"(acc[mf][nf][3])
                        : "r"(a[mf][0]), "r"(a[mf][1]), "r"(a[mf][2]), "r"(a[mf][3]),
                          "r"(b0), "r"(b1));
                }
            }
        }
        __syncthreads();
    }

    // fused attention logits
    float ps[2][2][2], pd[2][2][2];
    #pragma unroll
    for (int i = 0; i < 8; i++) { (&ps[0][0][0])[i] = 0.f; (&pd[0][0][0])[i] = 0.f; }

    #pragma unroll
    for (int nf = 0; nf < 8; nf++) {
        int hh = nf >> 2;
        int head = nw * 2 + hh;
        int cl = (nf & 3) * 8 + tig * 2;
        float as0 = att_src[head * 32 + cl], as1 = att_src[head * 32 + cl + 1];
        float ad0 = att_dst[head * 32 + cl], ad1 = att_dst[head * 32 + cl + 1];
        #pragma unroll
        for (int mf = 0; mf < 2; mf++) {
            ps[mf][0][hh] += acc[mf][nf][0] * as0 + acc[mf][nf][1] * as1;
            ps[mf][1][hh] += acc[mf][nf][2] * as0 + acc[mf][nf][3] * as1;
            pd[mf][0][hh] += acc[mf][nf][0] * ad0 + acc[mf][nf][1] * ad1;
            pd[mf][1][hh] += acc[mf][nf][2] * ad0 + acc[mf][nf][3] * ad1;
        }
    }
    #pragma unroll
    for (int i = 0; i < 8; i++) {
        float* pp = &ps[0][0][0];
        float* qq = &pd[0][0][0];
        pp[i] += __shfl_xor_sync(0xffffffffu, pp[i], 1);
        pp[i] += __shfl_xor_sync(0xffffffffu, pp[i], 2);
        qq[i] += __shfl_xor_sync(0xffffffffu, qq[i], 1);
        qq[i] += __shfl_xor_sync(0xffffffffu, qq[i], 2);
    }
    if (tig == 0) {
        #pragma unroll
        for (int mf = 0; mf < 2; mf++)
            #pragma unroll
            for (int rh = 0; rh < 2; rh++) {
                int r = row0 + mbase + mf * 16 + rh * 8 + gid;
                if (r < n) {
                    #pragma unroll
                    for (int hh = 0; hh < 2; hh++) {
                        g_asrc[r * NHEADS + nw * 2 + hh] = ps[mf][rh][hh];
                        g_adst[r * NHEADS + nw * 2 + hh] = pd[mf][rh][hh];
                    }
                }
            }
    }
    #pragma unroll
    for (int mf = 0; mf < 2; mf++) {
        int r = row0 + mbase + mf * 16 + gid;
        #pragma unroll
        for (int nf = 0; nf < 8; nf++) {
            int c = nbase + nf * 8 + tig * 2;
            if (r < n)
                *(float2*)&g_h[(size_t)r * FDIM + c] = make_float2(acc[mf][nf][0], acc[mf][nf][1]);
            if (r + 8 < n)
                *(float2*)&g_h[(size_t)(r + 8) * FDIM + c] = make_float2(acc[mf][nf][2], acc[mf][nf][3]);
        }
    }
}

// ---------------- CSR build ----------------
__global__ void k_hist(const void* __restrict__ ei, int E) {
    int e = blockIdx.x * blockDim.x + threadIdx.x;
    if (e >= E) return;
    int dst;
    if (g_idx64) dst = (int)((const long long*)ei)[(size_t)E + e];
    else         dst = ((const int*)ei)[(size_t)E + e];
    atomicAdd(&g_deg[dst], 1);
}

// single-block scan: 1024 threads x 52 ints, two passes + block scan of partials
__global__ __launch_bounds__(SCAN_T) void k_scan(int n) {
    __shared__ int sh[SCAN_T];
    int t = threadIdx.x;
    int base = t * SCAN_C;

    int sum = 0;
    #pragma unroll
    for (int q = 0; q < SCAN_C / 4; q++) {
        int4 v = *(const int4*)&g_deg[base + q * 4];
        sum += v.x + v.y + v.z + v.w;
    }
    sh[t] = sum;
    __syncthreads();
    for (int o = 1; o < SCAN_T; o <<= 1) {
        int x = (t >= o) ? sh[t - o] : 0;
        __syncthreads();
        sh[t] += x;
        __syncthreads();
    }
    int run = (t > 0) ? sh[t - 1] : 0;

    #pragma unroll
    for (int q = 0; q < SCAN_C / 4; q++) {
        int idx = base + q * 4;
        int4 v = *(const int4*)&g_deg[idx];
        int r0 = run + v.x;
        int r1 = r0 + v.y;
        int r2 = r1 + v.z;
        int r3 = r2 + v.w;
        if (idx < n)     { g_off[idx + 1] = r0; g_cur[idx]     = run; }
        if (idx + 1 < n) { g_off[idx + 2] = r1; g_cur[idx + 1] = r0; }
        if (idx + 2 < n) { g_off[idx + 3] = r2; g_cur[idx + 2] = r1; }
        if (idx + 3 < n) { g_off[idx + 4] = r3; g_cur[idx + 3] = r2; }
        run = r3;
    }
    if (t == 0) g_off[0] = 0;
}

__global__ void k_scatter(const void* __restrict__ ei, int E) {
    int e = blockIdx.x * blockDim.x + threadIdx.x;
    if (e >= E) return;
    int src, dst;
    load_edge(ei, e, E, src, dst);
    int pos = atomicAdd(&g_cur[dst], 1);
    g_sedge[pos] = ((unsigned long long)(unsigned)e << 32) | (unsigned)src;
}

// ---------------- aggregate: warp per dst, no output atomics ----------------
__global__ __launch_bounds__(256) void k_agg(float* __restrict__ out,
                                             float* __restrict__ apool,
                                             const float* __restrict__ bias,
                                             int n) {
    int dst = blockIdx.x * 8 + (threadIdx.x >> 5);
    int lane = threadIdx.x & 31;
    if (dst >= n) return;
    int off0 = g_off[dst];
    int deg = g_off[dst + 1] - off0;

    float4 adst = *(const float4*)&g_adst[dst * NHEADS];

    // pass A: exp + per-head sums (strided)
    float4 s = make_float4(0.f, 0.f, 0.f, 0.f);
    for (int j = lane; j < deg; j += 32) {
        unsigned long long se = g_sedge[off0 + j];
        int src = (int)(unsigned)se;
        float4 a = *(const float4*)&g_asrc[src * NHEADS];
        float4 ex;
        ex.x = lrelu_exp(a.x + adst.x);
        ex.y = lrelu_exp(a.y + adst.y);
        ex.z = lrelu_exp(a.z + adst.z);
        ex.w = lrelu_exp(a.w + adst.w);
        *(float4*)&g_exs[(size_t)(off0 + j) * NHEADS] = ex;
        s.x += ex.x; s.y += ex.y; s.z += ex.z; s.w += ex.w;
    }
    #pragma unroll
    for (int o = 16; o > 0; o >>= 1) {
        s.x += __shfl_xor_sync(0xffffffffu, s.x, o);
        s.y += __shfl_xor_sync(0xffffffffu, s.y, o);
        s.z += __shfl_xor_sync(0xffffffffu, s.z, o);
        s.w += __shfl_xor_sync(0xffffffffu, s.w, o);
    }
    int head = lane >> 3;
    float s_h = (head & 2) ? ((head & 1) ? s.w : s.z)
                           : ((head & 1) ? s.y : s.x);
    float rs_h = 1.0f / (s_h + GAT_EPS);

    // pass B: serial accumulation over edges + fused apool
    float4 acc = make_float4(0.f, 0.f, 0.f, 0.f);
    #pragma unroll 2
    for (int j = 0; j < deg; j++) {
        unsigned long long se = g_sedge[off0 + j];                  // broadcast
        int src = (int)(unsigned)se;
        float ex_h = g_exs[(size_t)(off0 + j) * NHEADS + head];     // 1 sector, bcast/4
        float c = ex_h * rs_h;
        float4 hv = *(const float4*)&g_h[(size_t)src * FDIM + lane * 4];
        acc.x = fmaf(c, hv.x, acc.x);
        acc.y = fmaf(c, hv.y, acc.y);
        acc.z = fmaf(c, hv.z, acc.z);
        acc.w = fmaf(c, hv.w, acc.w);
        // apool: sum of c over the 4 heads (uniform within each 8-lane group)
        float cs = c;
        cs += __shfl_xor_sync(0xffffffffu, cs, 8);
        cs += __shfl_xor_sync(0xffffffffu, cs, 16);
        if (lane == 0) apool[(int)(se >> 32)] = 0.25f * cs;
    }
    float4 bv = *(const float4*)&bias[lane * 4];
    acc.x += bv.x; acc.y += bv.y; acc.z += bv.z; acc.w += bv.w;
    *(float4*)&out[(size_t)dst * FDIM + lane * 4] = acc;
}

extern "C" void kernel_launch(void* const* d_in, const int* in_sizes, int n_in,
                              void* d_out, int out_size) {
    const float* x       = (const float*)d_in[0];
    const void*  ei      = d_in[1];
    const float* W       = (const float*)d_in[2];
    const float* att_src = (const float*)d_in[3];
    const float* att_dst = (const float*)d_in[4];
    const float* bias    = (const float*)d_in[5];

    int n = in_sizes[0] / FDIM;
    int E = in_sizes[1] / 2;

    float* out   = (float*)d_out;
    float* apool = out + (size_t)n * FDIM;

    k_init<<<(DEG_PAD + 255) / 256, 256>>>((const unsigned*)ei);
    k_gemm_att<<<(n + 127) / 128, 256>>>(x, W, att_src, att_dst, n);
    k_hist<<<(E + 255) / 256, 256>>>(ei, E);
    k_scan<<<1, SCAN_T>>>(n);
    k_scatter<<<(E + 255) / 256, 256>>>(ei, E);
    k_agg<<<(n + 7) / 8, 256>>>(out, apool, bias, n);
}

// round 6
// speedup vs baseline: 1.2768x; 1.2768x over previous
#include <cuda_runtime.h>
#include <cstdint>

#define MAXN 50000
#define MAXE 800000
#define NHEADS 4
#define FDIM 128
#define NEG_SLOPE 0.2f
#define GAT_EPS 1e-16f

// ---------------- scratch (static device globals; no allocation) ----------------
__device__ float g_h[(size_t)MAXN * FDIM];            // 25.6 MB: h = x @ W^T
__device__ float g_asrc[MAXN * NHEADS];               // per-node src logits
__device__ float g_adst[MAXN * NHEADS];               // per-node dst logits
__device__ int   g_deg[MAXN];                         // per-dst degree
__device__ int   g_off[MAXN + 1];                     // CSR offsets
__device__ int   g_cur[MAXN];                         // scatter cursors
__device__ int   g_bsum[512];                         // scan partials
__device__ unsigned long long g_sedge[MAXE];          // packed (eid<<32 | src), dst-sorted
__device__ float g_exs[(size_t)MAXE * NHEADS];        // exp(alpha), dst-sorted order
__device__ int   g_idx64;                             // 1 if edge_index is int64

// ---------------- helpers ----------------
__device__ __forceinline__ unsigned f2tf(float x) {
    unsigned u;
    asm("cvt.rna.tf32.f32 %0, %1;" : "=r"(u) : "f"(x));
    return u;
}
__device__ __forceinline__ float lrelu_exp(float v) {
    float a = v > 0.0f ? v : v * NEG_SLOPE;
    return __expf(a);
}
__device__ __forceinline__ void load_edge(const void* ei, int e, int E, int& src, int& dst) {
    if (g_idx64) {
        const long long* p = (const long long*)ei;
        src = (int)p[e];
        dst = (int)p[(size_t)E + e];
    } else {
        const int* p = (const int*)ei;
        src = p[e];
        dst = p[(size_t)E + e];
    }
}

// ---------------- zero degree counters + dtype detect (fused) ----------------
__global__ void k_zero(const unsigned* __restrict__ w, int n) {
    int i = blockIdx.x * blockDim.x + threadIdx.x;
    if (i < n) g_deg[i] = 0;
    if (i == 0) {
        int is64 = 1;
        #pragma unroll 8
        for (int k = 1; k < 256; k += 2) {
            if (w[k] != 0u) { is64 = 0; break; }
        }
        g_idx64 = is64;
    }
}

// ---------------- tf32 tensor-core GEMM + fused attention logits ----------------
#define SMST 136
__global__ __launch_bounds__(256) void k_gemm_att(const float* __restrict__ x,
                                                  const float* __restrict__ W,
                                                  const float* __restrict__ att_src,
                                                  const float* __restrict__ att_dst,
                                                  int n) {
    __shared__ float xs[32][SMST];   // xs[k][m]
    __shared__ float ws[32][SMST];   // ws[k][o]

    int tid = threadIdx.x;
    int lane = tid & 31, warp = tid >> 5;
    int gid = lane >> 2, tig = lane & 3;
    int mw = warp & 3, nw = warp >> 2;
    int mbase = mw * 32, nbase = nw * 64;
    int row0 = blockIdx.x * 128;

    float acc[2][8][4];
    #pragma unroll
    for (int mf = 0; mf < 2; mf++)
        #pragma unroll
        for (int nf = 0; nf < 8; nf++)
            #pragma unroll
            for (int r = 0; r < 4; r++) acc[mf][nf][r] = 0.0f;

    for (int kk = 0; kk < FDIM; kk += 32) {
        #pragma unroll
        for (int it = 0; it < 4; it++) {
            int v = tid + it * 256;
            int m = v & 127, kq = v >> 7;
            int gr = row0 + m;
            float4 xv = make_float4(0.f, 0.f, 0.f, 0.f);
            if (gr < n) xv = *(const float4*)&x[(size_t)gr * FDIM + kk + kq * 4];
            xs[kq * 4 + 0][m] = xv.x;
            xs[kq * 4 + 1][m] = xv.y;
            xs[kq * 4 + 2][m] = xv.z;
            xs[kq * 4 + 3][m] = xv.w;
            float4 wv = *(const float4*)&W[(size_t)m * FDIM + kk + kq * 4];
            ws[kq * 4 + 0][m] = wv.x;
            ws[kq * 4 + 1][m] = wv.y;
            ws[kq * 4 + 2][m] = wv.z;
            ws[kq * 4 + 3][m] = wv.w;
        }
        __syncthreads();

        #pragma unroll
        for (int ks = 0; ks < 4; ks++) {
            int k0 = ks * 8;
            unsigned a[2][4];
            #pragma unroll
            for (int mf = 0; mf < 2; mf++) {
                int r = mbase + mf * 16 + gid;
                a[mf][0] = f2tf(xs[k0 + tig][r]);
                a[mf][1] = f2tf(xs[k0 + tig][r + 8]);
                a[mf][2] = f2tf(xs[k0 + tig + 4][r]);
                a[mf][3] = f2tf(xs[k0 + tig + 4][r + 8]);
            }
            #pragma unroll
            for (int nf = 0; nf < 8; nf++) {
                int c = nbase + nf * 8 + gid;
                unsigned b0 = f2tf(ws[k0 + tig][c]);
                unsigned b1 = f2tf(ws[k0 + tig + 4][c]);
                #pragma unroll
                for (int mf = 0; mf < 2; mf++) {
                    asm volatile(
                        "mma.sync.aligned.m16n8k8.row.col.f32.tf32.tf32.f32 "
                        "{%0,%1,%2,%3}, {%4,%5,%6,%7}, {%8,%9}, {%0,%1,%2,%3};"
                        : "+f"(acc[mf][nf][0]), "+f"(acc[mf][nf][1]),
                          "+f"(acc[mf][nf][2]), "+f"(acc[mf][nf][3])
                        : "r"(a[mf][0]), "r"(a[mf][1]), "r"(a[mf][2]), "r"(a[mf][3]),
                          "r"(b0), "r"(b1));
                }
            }
        }
        __syncthreads();
    }

    // fused attention logits
    float ps[2][2][2], pd[2][2][2];
    #pragma unroll
    for (int i = 0; i < 8; i++) { (&ps[0][0][0])[i] = 0.f; (&pd[0][0][0])[i] = 0.f; }

    #pragma unroll
    for (int nf = 0; nf < 8; nf++) {
        int hh = nf >> 2;
        int head = nw * 2 + hh;
        int cl = (nf & 3) * 8 + tig * 2;
        float as0 = att_src[head * 32 + cl], as1 = att_src[head * 32 + cl + 1];
        float ad0 = att_dst[head * 32 + cl], ad1 = att_dst[head * 32 + cl + 1];
        #pragma unroll
        for (int mf = 0; mf < 2; mf++) {
            ps[mf][0][hh] += acc[mf][nf][0] * as0 + acc[mf][nf][1] * as1;
            ps[mf][1][hh] += acc[mf][nf][2] * as0 + acc[mf][nf][3] * as1;
            pd[mf][0][hh] += acc[mf][nf][0] * ad0 + acc[mf][nf][1] * ad1;
            pd[mf][1][hh] += acc[mf][nf][2] * ad0 + acc[mf][nf][3] * ad1;
        }
    }
    #pragma unroll
    for (int i = 0; i < 8; i++) {
        float* pp = &ps[0][0][0];
        float* qq = &pd[0][0][0];
        pp[i] += __shfl_xor_sync(0xffffffffu, pp[i], 1);
        pp[i] += __shfl_xor_sync(0xffffffffu, pp[i], 2);
        qq[i] += __shfl_xor_sync(0xffffffffu, qq[i], 1);
        qq[i] += __shfl_xor_sync(0xffffffffu, qq[i], 2);
    }
    if (tig == 0) {
        #pragma unroll
        for (int mf = 0; mf < 2; mf++)
            #pragma unroll
            for (int rh = 0; rh < 2; rh++) {
                int r = row0 + mbase + mf * 16 + rh * 8 + gid;
                if (r < n) {
                    #pragma unroll
                    for (int hh = 0; hh < 2; hh++) {
                        g_asrc[r * NHEADS + nw * 2 + hh] = ps[mf][rh][hh];
                        g_adst[r * NHEADS + nw * 2 + hh] = pd[mf][rh][hh];
                    }
                }
            }
    }
    #pragma unroll
    for (int mf = 0; mf < 2; mf++) {
        int r = row0 + mbase + mf * 16 + gid;
        #pragma unroll
        for (int nf = 0; nf < 8; nf++) {
            int c = nbase + nf * 8 + tig * 2;
            if (r < n)
                *(float2*)&g_h[(size_t)r * FDIM + c] = make_float2(acc[mf][nf][0], acc[mf][nf][1]);
            if (r + 8 < n)
                *(float2*)&g_h[(size_t)(r + 8) * FDIM + c] = make_float2(acc[mf][nf][2], acc[mf][nf][3]);
        }
    }
}

// ---------------- CSR build (multi-block scan chain, R3-proven) ----------------
__global__ void k_hist(const void* __restrict__ ei, int E) {
    int e = blockIdx.x * blockDim.x + threadIdx.x;
    if (e >= E) return;
    int dst;
    if (g_idx64) dst = (int)((const long long*)ei)[(size_t)E + e];
    else         dst = ((const int*)ei)[(size_t)E + e];
    atomicAdd(&g_deg[dst], 1);
}

__global__ void k_scan_blk(int n) {
    __shared__ int sh[256];
    int i = blockIdx.x * 256 + threadIdx.x;
    int v = (i < n) ? g_deg[i] : 0;
    sh[threadIdx.x] = v;
    __syncthreads();
    #pragma unroll
    for (int ofs = 1; ofs < 256; ofs <<= 1) {
        int t = (threadIdx.x >= ofs) ? sh[threadIdx.x - ofs] : 0;
        __syncthreads();
        sh[threadIdx.x] += t;
        __syncthreads();
    }
    if (i < n) g_off[i + 1] = sh[threadIdx.x];
    if (threadIdx.x == 255) g_bsum[blockIdx.x] = sh[255];
}

__global__ void k_scan_top(int nb) {
    __shared__ int sh[512];
    int t = threadIdx.x;
    int v = (t < nb) ? g_bsum[t] : 0;
    sh[t] = v;
    __syncthreads();
    #pragma unroll
    for (int ofs = 1; ofs < 512; ofs <<= 1) {
        int x = (t >= ofs) ? sh[t - ofs] : 0;
        __syncthreads();
        sh[t] += x;
        __syncthreads();
    }
    if (t < nb) g_bsum[t] = sh[t] - v;   // exclusive
}

__global__ void k_scan_add(int n) {
    int i = blockIdx.x * blockDim.x + threadIdx.x;
    if (i >= n) return;
    int add = g_bsum[i >> 8];
    int incl = g_off[i + 1] + add;
    g_off[i + 1] = incl;
    g_cur[i] = incl - g_deg[i];
    if (i == 0) g_off[0] = 0;
}

// ---------------- scatter + fused exp (logits are ready: runs after gemm_att) ----------------
__global__ void k_scatter(const void* __restrict__ ei, int E) {
    int e = blockIdx.x * blockDim.x + threadIdx.x;
    if (e >= E) return;
    int src, dst;
    load_edge(ei, e, E, src, dst);
    int pos = atomicAdd(&g_cur[dst], 1);
    g_sedge[pos] = ((unsigned long long)(unsigned)e << 32) | (unsigned)src;
    float4 a = *(const float4*)&g_asrc[src * NHEADS];
    float4 b = *(const float4*)&g_adst[dst * NHEADS];
    float4 ex;
    ex.x = lrelu_exp(a.x + b.x);
    ex.y = lrelu_exp(a.y + b.y);
    ex.z = lrelu_exp(a.z + b.z);
    ex.w = lrelu_exp(a.w + b.w);
    *(float4*)&g_exs[(size_t)pos * NHEADS] = ex;
}

// ---------------- aggregate: warp per dst, no output atomics ----------------
__global__ __launch_bounds__(256) void k_agg(float* __restrict__ out,
                                             float* __restrict__ apool,
                                             const float* __restrict__ bias,
                                             int n) {
    int dst = blockIdx.x * 8 + (threadIdx.x >> 5);
    int lane = threadIdx.x & 31;
    if (dst >= n) return;
    int off0 = g_off[dst];
    int deg = g_off[dst + 1] - off0;

    // pass A: per-head sums over precomputed exp (coalesced strided read)
    float4 s = make_float4(0.f, 0.f, 0.f, 0.f);
    for (int j = lane; j < deg; j += 32) {
        float4 ex = *(const float4*)&g_exs[(size_t)(off0 + j) * NHEADS];
        s.x += ex.x; s.y += ex.y; s.z += ex.z; s.w += ex.w;
    }
    #pragma unroll
    for (int o = 16; o > 0; o >>= 1) {
        s.x += __shfl_xor_sync(0xffffffffu, s.x, o);
        s.y += __shfl_xor_sync(0xffffffffu, s.y, o);
        s.z += __shfl_xor_sync(0xffffffffu, s.z, o);
        s.w += __shfl_xor_sync(0xffffffffu, s.w, o);
    }
    int head = lane >> 3;
    float s_h = (head & 2) ? ((head & 1) ? s.w : s.z)
                           : ((head & 1) ? s.y : s.x);
    float rs_h = 1.0f / (s_h + GAT_EPS);

    // pass B: serial accumulation over edges + fused apool
    float4 acc = make_float4(0.f, 0.f, 0.f, 0.f);
    #pragma unroll 2
    for (int j = 0; j < deg; j++) {
        unsigned long long se = g_sedge[off0 + j];                  // broadcast
        int src = (int)(unsigned)se;
        float ex_h = g_exs[(size_t)(off0 + j) * NHEADS + head];     // 1 sector, bcast/4
        float c = ex_h * rs_h;
        float4 hv = *(const float4*)&g_h[(size_t)src * FDIM + lane * 4];
        acc.x = fmaf(c, hv.x, acc.x);
        acc.y = fmaf(c, hv.y, acc.y);
        acc.z = fmaf(c, hv.z, acc.z);
        acc.w = fmaf(c, hv.w, acc.w);
        // apool: mean of c over heads (c uniform within each 8-lane group)
        float cs = c;
        cs += __shfl_xor_sync(0xffffffffu, cs, 8);
        cs += __shfl_xor_sync(0xffffffffu, cs, 16);
        if (lane == 0) apool[(int)(se >> 32)] = 0.25f * cs;
    }
    float4 bv = *(const float4*)&bias[lane * 4];
    acc.x += bv.x; acc.y += bv.y; acc.z += bv.z; acc.w += bv.w;
    *(float4*)&out[(size_t)dst * FDIM + lane * 4] = acc;
}

extern "C" void kernel_launch(void* const* d_in, const int* in_sizes, int n_in,
                              void* d_out, int out_size) {
    const float* x       = (const float*)d_in[0];
    const void*  ei      = d_in[1];
    const float* W       = (const float*)d_in[2];
    const float* att_src = (const float*)d_in[3];
    const float* att_dst = (const float*)d_in[4];
    const float* bias    = (const float*)d_in[5];

    int n = in_sizes[0] / FDIM;
    int E = in_sizes[1] / 2;

    float* out   = (float*)d_out;
    float* apool = out + (size_t)n * FDIM;

    int nb = (n + 255) / 256;

    k_zero<<<nb, 256>>>((const unsigned*)ei, n);
    k_gemm_att<<<(n + 127) / 128, 256>>>(x, W, att_src, att_dst, n);
    k_hist<<<(E + 255) / 256, 256>>>(ei, E);
    k_scan_blk<<<nb, 256>>>(n);
    k_scan_top<<<1, 512>>>(nb);
    k_scan_add<<<nb, 256>>>(n);
    k_scatter<<<(E + 255) / 256, 256>>>(ei, E);
    k_agg<<<(n + 7) / 8, 256>>>(out, apool, bias, n);
}

// round 8
// speedup vs baseline: 1.8432x; 1.4436x over previous
#include <cuda_runtime.h>
#include <cstdint>

#define MAXN 50000
#define MAXE 800000
#define NHEADS 4
#define FDIM 128
#define NEG_SLOPE 0.2f
#define GAT_EPS 1e-16f

// ---------------- scratch (static device globals; no allocation) ----------------
__device__ float g_h[(size_t)MAXN * FDIM];            // 25.6 MB: h = x @ W^T
__device__ float g_asrc[MAXN * NHEADS];               // per-node src logits
__device__ float g_adst[MAXN * NHEADS];               // per-node dst logits
__device__ int   g_deg[MAXN];                         // per-dst degree
__device__ int   g_off[MAXN + 1];                     // CSR offsets
__device__ int   g_cur[MAXN];                         // scatter cursors
__device__ int   g_bsum[512];                         // scan partials
__device__ unsigned long long g_sedge[MAXE];          // packed (eid<<32 | src), dst-sorted
__device__ float g_exs[(size_t)MAXE * NHEADS];        // exp(alpha), dst-sorted order
__device__ int   g_idx64;                             // 1 if edge_index is int64

// ---------------- helpers ----------------
__device__ __forceinline__ unsigned f2tf(float x) {
    unsigned u;
    asm("cvt.rna.tf32.f32 %0, %1;" : "=r"(u) : "f"(x));
    return u;
}
__device__ __forceinline__ float lrelu_exp(float v) {
    float a = v > 0.0f ? v : v * NEG_SLOPE;
    return __expf(a);
}
__device__ __forceinline__ void load_edge(const void* ei, int e, int E, int& src, int& dst) {
    if (g_idx64) {
        const long long* p = (const long long*)ei;
        src = (int)p[e];
        dst = (int)p[(size_t)E + e];
    } else {
        const int* p = (const int*)ei;
        src = p[e];
        dst = p[(size_t)E + e];
    }
}
__device__ __forceinline__ void cp16(float* dst_smem, const float* src, int srcsize) {
    uint32_t sa = (uint32_t)__cvta_generic_to_shared(dst_smem);
    asm volatile("cp.async.cg.shared.global [%0], [%1], 16, %2;"
                 :: "r"(sa), "l"(src), "r"(srcsize));
}

// ---------------- zero degree counters + dtype detect (fused) ----------------
__global__ void k_zero(const unsigned* __restrict__ w, int n) {
    int i = blockIdx.x * blockDim.x + threadIdx.x;
    if (i < n) g_deg[i] = 0;
    if (i == 0) {
        int is64 = 1;
        #pragma unroll 8
        for (int k = 1; k < 256; k += 2) {
            if (w[k] != 0u) { is64 = 0; break; }
        }
        g_idx64 = is64;
    }
}

// ---------------- tf32 tensor-core GEMM + fused attention logits ----------------
// Row-major smem tiles [m][k], stride 36 (bank = 4*gid + tig, conflict-free),
// cp.async double-buffered over 4 K-chunks of 32.
#define GST 36
#define GEMM_SMEM (4 * 128 * GST * 4)   // 2 bufs x 2 matrices = 73728 B
__global__ __launch_bounds__(256, 2) void k_gemm_att(const float* __restrict__ x,
                                                     const float* __restrict__ W,
                                                     const float* __restrict__ att_src,
                                                     const float* __restrict__ att_dst,
                                                     int n) {
    extern __shared__ float sm[];
    float* xs = sm;                       // [2][128][GST]
    float* ws = sm + 2 * 128 * GST;       // [2][128][GST]

    int tid = threadIdx.x;
    int lane = tid & 31, warp = tid >> 5;
    int gid = lane >> 2, tig = lane & 3;
    int mw = warp & 3, nw = warp >> 2;
    int mbase = mw * 32, nbase = nw * 64;
    int row0 = blockIdx.x * 128;

    float acc[2][8][4];
    #pragma unroll
    for (int mf = 0; mf < 2; mf++)
        #pragma unroll
        for (int nf = 0; nf < 8; nf++)
            #pragma unroll
            for (int r = 0; r < 4; r++) acc[mf][nf][r] = 0.0f;

    // chunk loader: 1024 16B copies per matrix, 4 per thread
    auto load_chunk = [&](int c) {
        int buf = c & 1;
        int kk = c * 32;
        #pragma unroll
        for (int it = 0; it < 4; it++) {
            int v = tid + it * 256;        // 0..1023
            int m = v >> 3, q = v & 7;
            int gr = row0 + m;
            const float* xsrc = (gr < n) ? &x[(size_t)gr * FDIM + kk + q * 4] : x;
            cp16(&xs[(buf * 128 + m) * GST + q * 4], xsrc, (gr < n) ? 16 : 0);
            cp16(&ws[(buf * 128 + m) * GST + q * 4], &W[(size_t)m * FDIM + kk + q * 4], 16);
        }
        asm volatile("cp.async.commit_group;");
    };

    load_chunk(0);
    for (int c = 0; c < 4; c++) {
        if (c < 3) {
            load_chunk(c + 1);
            asm volatile("cp.async.wait_group 1;");
        } else {
            asm volatile("cp.async.wait_group 0;");
        }
        __syncthreads();

        const float* xb = xs + (c & 1) * 128 * GST;
        const float* wb = ws + (c & 1) * 128 * GST;
        #pragma unroll
        for (int ks = 0; ks < 4; ks++) {
            int k0 = ks * 8;
            unsigned a[2][4];
            #pragma unroll
            for (int mf = 0; mf < 2; mf++) {
                int r = mbase + mf * 16 + gid;
                a[mf][0] = f2tf(xb[r * GST + k0 + tig]);
                a[mf][1] = f2tf(xb[(r + 8) * GST + k0 + tig]);
                a[mf][2] = f2tf(xb[r * GST + k0 + tig + 4]);
                a[mf][3] = f2tf(xb[(r + 8) * GST + k0 + tig + 4]);
            }
            #pragma unroll
            for (int nf = 0; nf < 8; nf++) {
                int cc = nbase + nf * 8 + gid;
                unsigned b0 = f2tf(wb[cc * GST + k0 + tig]);
                unsigned b1 = f2tf(wb[cc * GST + k0 + tig + 4]);
                #pragma unroll
                for (int mf = 0; mf < 2; mf++) {
                    asm volatile(
                        "mma.sync.aligned.m16n8k8.row.col.f32.tf32.tf32.f32 "
                        "{%0,%1,%2,%3}, {%4,%5,%6,%7}, {%8,%9}, {%0,%1,%2,%3};"
                        : "+f"(acc[mf][nf][0]), "+f"(acc[mf][nf][1]),
                          "+f"(acc[mf][nf][2]), "+f"(acc[mf][nf][3])
                        : "r"(a[mf][0]), "r"(a[mf][1]), "r"(a[mf][2]), "r"(a[mf][3]),
                          "r"(b0), "r"(b1));
                }
            }
        }
        __syncthreads();
    }

    // fused attention logits
    float ps[2][2][2], pd[2][2][2];
    #pragma unroll
    for (int i = 0; i < 8; i++) { (&ps[0][0][0])[i] = 0.f; (&pd[0][0][0])[i] = 0.f; }

    #pragma unroll
    for (int nf = 0; nf < 8; nf++) {
        int hh = nf >> 2;
        int head = nw * 2 + hh;
        int cl = (nf & 3) * 8 + tig * 2;
        float as0 = att_src[head * 32 + cl], as1 = att_src[head * 32 + cl + 1];
        float ad0 = att_dst[head * 32 + cl], ad1 = att_dst[head * 32 + cl + 1];
        #pragma unroll
        for (int mf = 0; mf < 2; mf++) {
            ps[mf][0][hh] += acc[mf][nf][0] * as0 + acc[mf][nf][1] * as1;
            ps[mf][1][hh] += acc[mf][nf][2] * as0 + acc[mf][nf][3] * as1;
            pd[mf][0][hh] += acc[mf][nf][0] * ad0 + acc[mf][nf][1] * ad1;
            pd[mf][1][hh] += acc[mf][nf][2] * ad0 + acc[mf][nf][3] * ad1;
        }
    }
    #pragma unroll
    for (int i = 0; i < 8; i++) {
        float* pp = &ps[0][0][0];
        float* qq = &pd[0][0][0];
        pp[i] += __shfl_xor_sync(0xffffffffu, pp[i], 1);
        pp[i] += __shfl_xor_sync(0xffffffffu, pp[i], 2);
        qq[i] += __shfl_xor_sync(0xffffffffu, qq[i], 1);
        qq[i] += __shfl_xor_sync(0xffffffffu, qq[i], 2);
    }
    if (tig == 0) {
        #pragma unroll
        for (int mf = 0; mf < 2; mf++)
            #pragma unroll
            for (int rh = 0; rh < 2; rh++) {
                int r = row0 + mbase + mf * 16 + rh * 8 + gid;
                if (r < n) {
                    #pragma unroll
                    for (int hh = 0; hh < 2; hh++) {
                        g_asrc[r * NHEADS + nw * 2 + hh] = ps[mf][rh][hh];
                        g_adst[r * NHEADS + nw * 2 + hh] = pd[mf][rh][hh];
                    }
                }
            }
    }
    #pragma unroll
    for (int mf = 0; mf < 2; mf++) {
        int r = row0 + mbase + mf * 16 + gid;
        #pragma unroll
        for (int nf = 0; nf < 8; nf++) {
            int c = nbase + nf * 8 + tig * 2;
            if (r < n)
                *(float2*)&g_h[(size_t)r * FDIM + c] = make_float2(acc[mf][nf][0], acc[mf][nf][1]);
            if (r + 8 < n)
                *(float2*)&g_h[(size_t)(r + 8) * FDIM + c] = make_float2(acc[mf][nf][2], acc[mf][nf][3]);
        }
    }
}

// ---------------- CSR build (R3-proven) ----------------
__global__ void k_hist(const void* __restrict__ ei, int E) {
    int e = blockIdx.x * blockDim.x + threadIdx.x;
    if (e >= E) return;
    int dst;
    if (g_idx64) dst = (int)((const long long*)ei)[(size_t)E + e];
    else         dst = ((const int*)ei)[(size_t)E + e];
    atomicAdd(&g_deg[dst], 1);
}

__global__ void k_scan_blk(int n) {
    __shared__ int sh[256];
    int i = blockIdx.x * 256 + threadIdx.x;
    int v = (i < n) ? g_deg[i] : 0;
    sh[threadIdx.x] = v;
    __syncthreads();
    #pragma unroll
    for (int ofs = 1; ofs < 256; ofs <<= 1) {
        int t = (threadIdx.x >= ofs) ? sh[threadIdx.x - ofs] : 0;
        __syncthreads();
        sh[threadIdx.x] += t;
        __syncthreads();
    }
    if (i < n) g_off[i + 1] = sh[threadIdx.x];
    if (threadIdx.x == 255) g_bsum[blockIdx.x] = sh[255];
}

// merged top-scan + add: each block scans the (<=256) partials locally
__global__ void k_scan_add(int n, int nb) {
    __shared__ int sh[256];
    int t = threadIdx.x;
    int v = (t < nb) ? g_bsum[t] : 0;
    sh[t] = v;
    __syncthreads();
    #pragma unroll
    for (int ofs = 1; ofs < 256; ofs <<= 1) {
        int x = (t >= ofs) ? sh[t - ofs] : 0;
        __syncthreads();
        sh[t] += x;
        __syncthreads();
    }
    int add = (blockIdx.x > 0) ? sh[blockIdx.x - 1] : 0;   // exclusive prefix of this block
    int i = blockIdx.x * 256 + t;
    if (i >= n) return;
    int incl = g_off[i + 1] + add;
    g_off[i + 1] = incl;
    g_cur[i] = incl - g_deg[i];
    if (i == 0) g_off[0] = 0;
}

__global__ void k_scatter(const void* __restrict__ ei, int E) {
    int e = blockIdx.x * blockDim.x + threadIdx.x;
    if (e >= E) return;
    int src, dst;
    load_edge(ei, e, E, src, dst);
    int pos = atomicAdd(&g_cur[dst], 1);
    g_sedge[pos] = ((unsigned long long)(unsigned)e << 32) | (unsigned)src;
}

// ---------------- aggregate: warp per dst, no output atomics (R3-proven) ----------------
__global__ __launch_bounds__(256) void k_agg(float* __restrict__ out,
                                             float* __restrict__ apool,
                                             const float* __restrict__ bias,
                                             int n) {
    int dst = blockIdx.x * 8 + (threadIdx.x >> 5);
    int lane = threadIdx.x & 31;
    if (dst >= n) return;
    int off0 = g_off[dst];
    int deg = g_off[dst + 1] - off0;

    float4 adst = *(const float4*)&g_adst[dst * NHEADS];

    // pass A: exp + per-head sums (strided)
    float4 s = make_float4(0.f, 0.f, 0.f, 0.f);
    for (int j = lane; j < deg; j += 32) {
        unsigned long long se = g_sedge[off0 + j];
        int src = (int)(unsigned)se;
        float4 a = *(const float4*)&g_asrc[src * NHEADS];
        float4 ex;
        ex.x = lrelu_exp(a.x + adst.x);
        ex.y = lrelu_exp(a.y + adst.y);
        ex.z = lrelu_exp(a.z + adst.z);
        ex.w = lrelu_exp(a.w + adst.w);
        *(float4*)&g_exs[(size_t)(off0 + j) * NHEADS] = ex;
        s.x += ex.x; s.y += ex.y; s.z += ex.z; s.w += ex.w;
    }
    #pragma unroll
    for (int o = 16; o > 0; o >>= 1) {
        s.x += __shfl_xor_sync(0xffffffffu, s.x, o);
        s.y += __shfl_xor_sync(0xffffffffu, s.y, o);
        s.z += __shfl_xor_sync(0xffffffffu, s.z, o);
        s.w += __shfl_xor_sync(0xffffffffu, s.w, o);
    }
    float4 rs;
    rs.x = 1.0f / (s.x + GAT_EPS);
    rs.y = 1.0f / (s.y + GAT_EPS);
    rs.z = 1.0f / (s.z + GAT_EPS);
    rs.w = 1.0f / (s.w + GAT_EPS);

    // pass A2: apool (strided)
    for (int j = lane; j < deg; j += 32) {
        float4 ex = *(const float4*)&g_exs[(size_t)(off0 + j) * NHEADS];
        int e = (int)(g_sedge[off0 + j] >> 32);
        apool[e] = 0.25f * (ex.x * rs.x + ex.y * rs.y + ex.z * rs.z + ex.w * rs.w);
    }

    // pass B: serial accumulation over edges, full warp per h row
    int head = lane >> 3;
    float rs_h = (head & 2) ? ((head & 1) ? rs.w : rs.z)
                            : ((head & 1) ? rs.y : rs.x);
    float4 acc = make_float4(0.f, 0.f, 0.f, 0.f);
    for (int j = 0; j < deg; j++) {
        unsigned long long se = g_sedge[off0 + j];          // broadcast
        int src = (int)(unsigned)se;
        float4 ex = *(const float4*)&g_exs[(size_t)(off0 + j) * NHEADS];  // broadcast
        float ex_h = (head & 2) ? ((head & 1) ? ex.w : ex.z)
                                : ((head & 1) ? ex.y : ex.x);
        float c = ex_h * rs_h;
        float4 hv = *(const float4*)&g_h[(size_t)src * FDIM + lane * 4];
        acc.x = fmaf(c, hv.x, acc.x);
        acc.y = fmaf(c, hv.y, acc.y);
        acc.z = fmaf(c, hv.z, acc.z);
        acc.w = fmaf(c, hv.w, acc.w);
    }
    float4 bv = *(const float4*)&bias[lane * 4];
    acc.x += bv.x; acc.y += bv.y; acc.z += bv.z; acc.w += bv.w;
    *(float4*)&out[(size_t)dst * FDIM + lane * 4] = acc;
}

extern "C" void kernel_launch(void* const* d_in, const int* in_sizes, int n_in,
                              void* d_out, int out_size) {
    const float* x       = (const float*)d_in[0];
    const void*  ei      = d_in[1];
    const float* W       = (const float*)d_in[2];
    const float* att_src = (const float*)d_in[3];
    const float* att_dst = (const float*)d_in[4];
    const float* bias    = (const float*)d_in[5];

    int n = in_sizes[0] / FDIM;
    int E = in_sizes[1] / 2;

    float* out   = (float*)d_out;
    float* apool = out + (size_t)n * FDIM;

    int nb = (n + 255) / 256;

    static int smem_set = 0;
    if (!smem_set) {
        cudaFuncSetAttribute(k_gemm_att, cudaFuncAttributeMaxDynamicSharedMemorySize, GEMM_SMEM);
        smem_set = 1;
    }

    k_zero<<<nb, 256>>>((const unsigned*)ei, n);
    k_gemm_att<<<(n + 127) / 128, 256, GEMM_SMEM>>>(x, W, att_src, att_dst, n);
    k_hist<<<(E + 255) / 256, 256>>>(ei, E);
    k_scan_blk<<<nb, 256>>>(n);
    k_scan_add<<<nb, 256>>>(n, nb);
    k_scatter<<<(E + 255) / 256, 256>>>(ei, E);
    k_agg<<<(n + 7) / 8, 256>>>(out, apool, bias, n);
}

// round 9
// speedup vs baseline: 1.9341x; 1.0493x over previous
#include <cuda_runtime.h>
#include <cuda_fp16.h>
#include <cstdint>

#define MAXN 50000
#define MAXE 800000
#define NHEADS 4
#define FDIM 128
#define NEG_SLOPE 0.2f
#define GAT_EPS 1e-16f

// ---------------- scratch (static device globals; no allocation) ----------------
__device__ __half g_h[(size_t)MAXN * FDIM];           // 12.8 MB: h = x @ W^T (fp16)
__device__ float g_asrc[MAXN * NHEADS];               // per-node src logits
__device__ float g_adst[MAXN * NHEADS];               // per-node dst logits
__device__ int   g_deg[MAXN];                         // per-dst degree
__device__ int   g_off[MAXN + 1];                     // CSR offsets
__device__ int   g_cur[MAXN];                         // scatter cursors
__device__ int   g_bsum[512];                         // scan partials
__device__ unsigned long long g_sedge[MAXE];          // packed (eid<<32 | src), dst-sorted
__device__ float g_exs[(size_t)MAXE * NHEADS];        // exp(alpha), dst-sorted order
__device__ int   g_idx64;                             // 1 if edge_index is int64

// ---------------- helpers ----------------
__device__ __forceinline__ unsigned f2tf(float x) {
    unsigned u;
    asm("cvt.rna.tf32.f32 %0, %1;" : "=r"(u) : "f"(x));
    return u;
}
__device__ __forceinline__ float lrelu_exp(float v) {
    float a = v > 0.0f ? v : v * NEG_SLOPE;
    return __expf(a);
}
__device__ __forceinline__ void load_edge(const void* ei, int e, int E, int& src, int& dst) {
    if (g_idx64) {
        const long long* p = (const long long*)ei;
        src = (int)p[e];
        dst = (int)p[(size_t)E + e];
    } else {
        const int* p = (const int*)ei;
        src = p[e];
        dst = p[(size_t)E + e];
    }
}
__device__ __forceinline__ void cp16(float* dst_smem, const float* src, int srcsize) {
    uint32_t sa = (uint32_t)__cvta_generic_to_shared(dst_smem);
    asm volatile("cp.async.cg.shared.global [%0], [%1], 16, %2;"
                 :: "r"(sa), "l"(src), "r"(srcsize));
}

// ---------------- zero degree counters + dtype detect (fused) ----------------
__global__ void k_zero(const unsigned* __restrict__ w, int n) {
    int i = blockIdx.x * blockDim.x + threadIdx.x;
    if (i < n) g_deg[i] = 0;
    if (i == 0) {
        int is64 = 1;
        #pragma unroll 8
        for (int k = 1; k < 256; k += 2) {
            if (w[k] != 0u) { is64 = 0; break; }
        }
        g_idx64 = is64;
    }
}

// ---------------- tf32 tensor-core GEMM + fused attention logits ----------------
// Row-major smem tiles [m][k], stride 36, cp.async double-buffered, 4 K-chunks.
#define GST 36
#define GEMM_SMEM (4 * 128 * GST * 4)   // 73728 B
__global__ __launch_bounds__(256, 2) void k_gemm_att(const float* __restrict__ x,
                                                     const float* __restrict__ W,
                                                     const float* __restrict__ att_src,
                                                     const float* __restrict__ att_dst,
                                                     int n) {
    extern __shared__ float sm[];
    float* xs = sm;                       // [2][128][GST]
    float* ws = sm + 2 * 128 * GST;       // [2][128][GST]

    int tid = threadIdx.x;
    int lane = tid & 31, warp = tid >> 5;
    int gid = lane >> 2, tig = lane & 3;
    int mw = warp & 3, nw = warp >> 2;
    int mbase = mw * 32, nbase = nw * 64;
    int row0 = blockIdx.x * 128;

    float acc[2][8][4];
    #pragma unroll
    for (int mf = 0; mf < 2; mf++)
        #pragma unroll
        for (int nf = 0; nf < 8; nf++)
            #pragma unroll
            for (int r = 0; r < 4; r++) acc[mf][nf][r] = 0.0f;

    auto load_chunk = [&](int c) {
        int buf = c & 1;
        int kk = c * 32;
        #pragma unroll
        for (int it = 0; it < 4; it++) {
            int v = tid + it * 256;        // 0..1023
            int m = v >> 3, q = v & 7;
            int gr = row0 + m;
            const float* xsrc = (gr < n) ? &x[(size_t)gr * FDIM + kk + q * 4] : x;
            cp16(&xs[(buf * 128 + m) * GST + q * 4], xsrc, (gr < n) ? 16 : 0);
            cp16(&ws[(buf * 128 + m) * GST + q * 4], &W[(size_t)m * FDIM + kk + q * 4], 16);
        }
        asm volatile("cp.async.commit_group;");
    };

    load_chunk(0);
    for (int c = 0; c < 4; c++) {
        if (c < 3) {
            load_chunk(c + 1);
            asm volatile("cp.async.wait_group 1;");
        } else {
            asm volatile("cp.async.wait_group 0;");
        }
        __syncthreads();

        const float* xb = xs + (c & 1) * 128 * GST;
        const float* wb = ws + (c & 1) * 128 * GST;
        #pragma unroll
        for (int ks = 0; ks < 4; ks++) {
            int k0 = ks * 8;
            unsigned a[2][4];
            #pragma unroll
            for (int mf = 0; mf < 2; mf++) {
                int r = mbase + mf * 16 + gid;
                a[mf][0] = f2tf(xb[r * GST + k0 + tig]);
                a[mf][1] = f2tf(xb[(r + 8) * GST + k0 + tig]);
                a[mf][2] = f2tf(xb[r * GST + k0 + tig + 4]);
                a[mf][3] = f2tf(xb[(r + 8) * GST + k0 + tig + 4]);
            }
            #pragma unroll
            for (int nf = 0; nf < 8; nf++) {
                int cc = nbase + nf * 8 + gid;
                unsigned b0 = f2tf(wb[cc * GST + k0 + tig]);
                unsigned b1 = f2tf(wb[cc * GST + k0 + tig + 4]);
                #pragma unroll
                for (int mf = 0; mf < 2; mf++) {
                    asm volatile(
                        "mma.sync.aligned.m16n8k8.row.col.f32.tf32.tf32.f32 "
                        "{%0,%1,%2,%3}, {%4,%5,%6,%7}, {%8,%9}, {%0,%1,%2,%3};"
                        : "+f"(acc[mf][nf][0]), "+f"(acc[mf][nf][1]),
                          "+f"(acc[mf][nf][2]), "+f"(acc[mf][nf][3])
                        : "r"(a[mf][0]), "r"(a[mf][1]), "r"(a[mf][2]), "r"(a[mf][3]),
                          "r"(b0), "r"(b1));
                }
            }
        }
        __syncthreads();
    }

    // fused attention logits (from fp32 accumulators — full precision)
    float ps[2][2][2], pd[2][2][2];
    #pragma unroll
    for (int i = 0; i < 8; i++) { (&ps[0][0][0])[i] = 0.f; (&pd[0][0][0])[i] = 0.f; }

    #pragma unroll
    for (int nf = 0; nf < 8; nf++) {
        int hh = nf >> 2;
        int head = nw * 2 + hh;
        int cl = (nf & 3) * 8 + tig * 2;
        float as0 = att_src[head * 32 + cl], as1 = att_src[head * 32 + cl + 1];
        float ad0 = att_dst[head * 32 + cl], ad1 = att_dst[head * 32 + cl + 1];
        #pragma unroll
        for (int mf = 0; mf < 2; mf++) {
            ps[mf][0][hh] += acc[mf][nf][0] * as0 + acc[mf][nf][1] * as1;
            ps[mf][1][hh] += acc[mf][nf][2] * as0 + acc[mf][nf][3] * as1;
            pd[mf][0][hh] += acc[mf][nf][0] * ad0 + acc[mf][nf][1] * ad1;
            pd[mf][1][hh] += acc[mf][nf][2] * ad0 + acc[mf][nf][3] * ad1;
        }
    }
    #pragma unroll
    for (int i = 0; i < 8; i++) {
        float* pp = &ps[0][0][0];
        float* qq = &pd[0][0][0];
        pp[i] += __shfl_xor_sync(0xffffffffu, pp[i], 1);
        pp[i] += __shfl_xor_sync(0xffffffffu, pp[i], 2);
        qq[i] += __shfl_xor_sync(0xffffffffu, qq[i], 1);
        qq[i] += __shfl_xor_sync(0xffffffffu, qq[i], 2);
    }
    if (tig == 0) {
        #pragma unroll
        for (int mf = 0; mf < 2; mf++)
            #pragma unroll
            for (int rh = 0; rh < 2; rh++) {
                int r = row0 + mbase + mf * 16 + rh * 8 + gid;
                if (r < n) {
                    #pragma unroll
                    for (int hh = 0; hh < 2; hh++) {
                        g_asrc[r * NHEADS + nw * 2 + hh] = ps[mf][rh][hh];
                        g_adst[r * NHEADS + nw * 2 + hh] = pd[mf][rh][hh];
                    }
                }
            }
    }
    // store h as fp16 (half2 per 2 consecutive cols)
    #pragma unroll
    for (int mf = 0; mf < 2; mf++) {
        int r = row0 + mbase + mf * 16 + gid;
        #pragma unroll
        for (int nf = 0; nf < 8; nf++) {
            int c = nbase + nf * 8 + tig * 2;
            if (r < n)
                *(half2*)&g_h[(size_t)r * FDIM + c] = __floats2half2_rn(acc[mf][nf][0], acc[mf][nf][1]);
            if (r + 8 < n)
                *(half2*)&g_h[(size_t)(r + 8) * FDIM + c] = __floats2half2_rn(acc[mf][nf][2], acc[mf][nf][3]);
        }
    }
}

// ---------------- CSR build ----------------
__global__ void k_hist(const void* __restrict__ ei, int E) {
    int e = blockIdx.x * blockDim.x + threadIdx.x;
    if (e >= E) return;
    int dst;
    if (g_idx64) dst = (int)((const long long*)ei)[(size_t)E + e];
    else         dst = ((const int*)ei)[(size_t)E + e];
    atomicAdd(&g_deg[dst], 1);
}

__global__ void k_scan_blk(int n) {
    __shared__ int sh[256];
    int i = blockIdx.x * 256 + threadIdx.x;
    int v = (i < n) ? g_deg[i] : 0;
    sh[threadIdx.x] = v;
    __syncthreads();
    #pragma unroll
    for (int ofs = 1; ofs < 256; ofs <<= 1) {
        int t = (threadIdx.x >= ofs) ? sh[threadIdx.x - ofs] : 0;
        __syncthreads();
        sh[threadIdx.x] += t;
        __syncthreads();
    }
    if (i < n) g_off[i + 1] = sh[threadIdx.x];
    if (threadIdx.x == 255) g_bsum[blockIdx.x] = sh[255];
}

__global__ void k_scan_add(int n, int nb) {
    __shared__ int sh[256];
    int t = threadIdx.x;
    int v = (t < nb) ? g_bsum[t] : 0;
    sh[t] = v;
    __syncthreads();
    #pragma unroll
    for (int ofs = 1; ofs < 256; ofs <<= 1) {
        int x = (t >= ofs) ? sh[t - ofs] : 0;
        __syncthreads();
        sh[t] += x;
        __syncthreads();
    }
    int add = (blockIdx.x > 0) ? sh[blockIdx.x - 1] : 0;
    int i = blockIdx.x * 256 + t;
    if (i >= n) return;
    int incl = g_off[i + 1] + add;
    g_off[i + 1] = incl;
    g_cur[i] = incl - g_deg[i];
    if (i == 0) g_off[0] = 0;
}

__global__ void k_scatter(const void* __restrict__ ei, int E) {
    int e = blockIdx.x * blockDim.x + threadIdx.x;
    if (e >= E) return;
    int src, dst;
    load_edge(ei, e, E, src, dst);
    int pos = atomicAdd(&g_cur[dst], 1);
    g_sedge[pos] = ((unsigned long long)(unsigned)e << 32) | (unsigned)src;
}

// ---------------- aggregate: warp per dst, no output atomics ----------------
__global__ __launch_bounds__(256) void k_agg(float* __restrict__ out,
                                             float* __restrict__ apool,
                                             const float* __restrict__ bias,
                                             int n) {
    int dst = blockIdx.x * 8 + (threadIdx.x >> 5);
    int lane = threadIdx.x & 31;
    if (dst >= n) return;
    int off0 = g_off[dst];
    int deg = g_off[dst + 1] - off0;

    float4 adst = *(const float4*)&g_adst[dst * NHEADS];

    // pass A: exp + per-head sums (strided)
    float4 s = make_float4(0.f, 0.f, 0.f, 0.f);
    for (int j = lane; j < deg; j += 32) {
        unsigned long long se = g_sedge[off0 + j];
        int src = (int)(unsigned)se;
        float4 a = *(const float4*)&g_asrc[src * NHEADS];
        float4 ex;
        ex.x = lrelu_exp(a.x + adst.x);
        ex.y = lrelu_exp(a.y + adst.y);
        ex.z = lrelu_exp(a.z + adst.z);
        ex.w = lrelu_exp(a.w + adst.w);
        *(float4*)&g_exs[(size_t)(off0 + j) * NHEADS] = ex;
        s.x += ex.x; s.y += ex.y; s.z += ex.z; s.w += ex.w;
    }
    #pragma unroll
    for (int o = 16; o > 0; o >>= 1) {
        s.x += __shfl_xor_sync(0xffffffffu, s.x, o);
        s.y += __shfl_xor_sync(0xffffffffu, s.y, o);
        s.z += __shfl_xor_sync(0xffffffffu, s.z, o);
        s.w += __shfl_xor_sync(0xffffffffu, s.w, o);
    }
    float4 rs;
    rs.x = 1.0f / (s.x + GAT_EPS);
    rs.y = 1.0f / (s.y + GAT_EPS);
    rs.z = 1.0f / (s.z + GAT_EPS);
    rs.w = 1.0f / (s.w + GAT_EPS);

    // pass A2: apool (strided)
    for (int j = lane; j < deg; j += 32) {
        float4 ex = *(const float4*)&g_exs[(size_t)(off0 + j) * NHEADS];
        int e = (int)(g_sedge[off0 + j] >> 32);
        apool[e] = 0.25f * (ex.x * rs.x + ex.y * rs.y + ex.z * rs.z + ex.w * rs.w);
    }

    // pass B: serial accumulation over edges, fp16 h gather (8 B/lane/edge)
    int head = lane >> 3;
    float rs_h = (head & 2) ? ((head & 1) ? rs.w : rs.z)
                            : ((head & 1) ? rs.y : rs.x);
    float4 acc = make_float4(0.f, 0.f, 0.f, 0.f);
    for (int j = 0; j < deg; j++) {
        unsigned long long se = g_sedge[off0 + j];          // broadcast
        int src = (int)(unsigned)se;
        float4 ex = *(const float4*)&g_exs[(size_t)(off0 + j) * NHEADS];  // broadcast
        float ex_h = (head & 2) ? ((head & 1) ? ex.w : ex.z)
                                : ((head & 1) ? ex.y : ex.x);
        float c = ex_h * rs_h;
        uint2 hraw = *(const uint2*)&g_h[(size_t)src * FDIM + lane * 4];
        float2 h01 = __half22float2(*(const half2*)&hraw.x);
        float2 h23 = __half22float2(*(const half2*)&hraw.y);
        acc.x = fmaf(c, h01.x, acc.x);
        acc.y = fmaf(c, h01.y, acc.y);
        acc.z = fmaf(c, h23.x, acc.z);
        acc.w = fmaf(c, h23.y, acc.w);
    }
    float4 bv = *(const float4*)&bias[lane * 4];
    acc.x += bv.x; acc.y += bv.y; acc.z += bv.z; acc.w += bv.w;
    *(float4*)&out[(size_t)dst * FDIM + lane * 4] = acc;
}

extern "C" void kernel_launch(void* const* d_in, const int* in_sizes, int n_in,
                              void* d_out, int out_size) {
    const float* x       = (const float*)d_in[0];
    const void*  ei      = d_in[1];
    const float* W       = (const float*)d_in[2];
    const float* att_src = (const float*)d_in[3];
    const float* att_dst = (const float*)d_in[4];
    const float* bias    = (const float*)d_in[5];

    int n = in_sizes[0] / FDIM;
    int E = in_sizes[1] / 2;

    float* out   = (float*)d_out;
    float* apool = out + (size_t)n * FDIM;

    int nb = (n + 255) / 256;

    static int smem_set = 0;
    if (!smem_set) {
        cudaFuncSetAttribute(k_gemm_att, cudaFuncAttributeMaxDynamicSharedMemorySize, GEMM_SMEM);
        smem_set = 1;
    }

    k_zero<<<nb, 256>>>((const unsigned*)ei, n);
    k_gemm_att<<<(n + 127) / 128, 256, GEMM_SMEM>>>(x, W, att_src, att_dst, n);
    k_hist<<<(E + 255) / 256, 256>>>(ei, E);
    k_scan_blk<<<nb, 256>>>(n);
    k_scan_add<<<nb, 256>>>(n, nb);
    k_scatter<<<(E + 255) / 256, 256>>>(ei, E);
    k_agg<<<(n + 7) / 8, 256>>>(out, apool, bias, n);
}

// round 11
// speedup vs baseline: 2.1090x; 1.0905x over previous
#include <cuda_runtime.h>
#include <cuda_fp16.h>
#include <cstdint>

#define MAXN 50000
#define MAXE 800000
#define NHEADS 4
#define FDIM 128
#define NEG_SLOPE 0.2f
#define GAT_EPS 1e-16f

// ---------------- scratch (static device globals; no allocation) ----------------
__device__ __half g_h[(size_t)MAXN * FDIM];           // 12.8 MB: h = x @ W^T (fp16)
__device__ float g_asrc[MAXN * NHEADS];               // per-node src logits
__device__ float g_adst[MAXN * NHEADS];               // per-node dst logits
__device__ int   g_deg[MAXN];                         // per-dst degree (zeroed by k_agg)
__device__ int   g_off[MAXN + 1];                     // CSR offsets
__device__ int   g_cur[MAXN];                         // scatter cursors
__device__ int   g_bsum[512];                         // scan partials
__device__ unsigned long long g_sedge[MAXE];          // packed (eid<<32 | src), dst-sorted
__device__ float g_exs[(size_t)MAXE * NHEADS];        // exp(alpha), dst-sorted order
__device__ int   g_idx64;                             // 1 if edge_index is int64

// ---------------- helpers ----------------
__device__ __forceinline__ unsigned f2tf(float x) {
    unsigned u;
    asm("cvt.rna.tf32.f32 %0, %1;" : "=r"(u) : "f"(x));
    return u;
}
__device__ __forceinline__ float lrelu_exp(float v) {
    float a = v > 0.0f ? v : v * NEG_SLOPE;
    return __expf(a);
}
__device__ __forceinline__ void load_edge(const void* ei, int e, int E, int& src, int& dst) {
    if (g_idx64) {
        const long long* p = (const long long*)ei;
        src = (int)p[e];
        dst = (int)p[(size_t)E + e];
    } else {
        const int* p = (const int*)ei;
        src = p[e];
        dst = p[(size_t)E + e];
    }
}
__device__ __forceinline__ void cp16(float* dst_smem, const float* src, int srcsize) {
    uint32_t sa = (uint32_t)__cvta_generic_to_shared(dst_smem);
    asm volatile("cp.async.cg.shared.global [%0], [%1], 16, %2;"
                 :: "r"(sa), "l"(src), "r"(srcsize));
}

// ---------------- tf32 tensor-core GEMM + fused attention logits + dtype detect ----------------
#define GST 36
#define GEMM_SMEM (4 * 128 * GST * 4)   // 73728 B
__global__ __launch_bounds__(256, 2) void k_gemm_att(const float* __restrict__ x,
                                                     const float* __restrict__ W,
                                                     const float* __restrict__ att_src,
                                                     const float* __restrict__ att_dst,
                                                     const unsigned* __restrict__ eiw,
                                                     int n) {
    extern __shared__ float sm[];
    float* xs = sm;                       // [2][128][GST]
    float* ws = sm + 2 * 128 * GST;       // [2][128][GST]

    int tid = threadIdx.x;

    // dtype detect (completes before k_hist at the kernel boundary)
    if (blockIdx.x == 0 && tid == 0) {
        int is64 = 1;
        #pragma unroll 8
        for (int k = 1; k < 256; k += 2) {
            if (eiw[k] != 0u) { is64 = 0; break; }
        }
        g_idx64 = is64;
    }

    int lane = tid & 31, warp = tid >> 5;
    int gid = lane >> 2, tig = lane & 3;
    int mw = warp & 3, nw = warp >> 2;
    int mbase = mw * 32, nbase = nw * 64;
    int row0 = blockIdx.x * 128;

    float acc[2][8][4];
    #pragma unroll
    for (int mf = 0; mf < 2; mf++)
        #pragma unroll
        for (int nf = 0; nf < 8; nf++)
            #pragma unroll
            for (int r = 0; r < 4; r++) acc[mf][nf][r] = 0.0f;

    auto load_chunk = [&](int c) {
        int buf = c & 1;
        int kk = c * 32;
        #pragma unroll
        for (int it = 0; it < 4; it++) {
            int v = tid + it * 256;        // 0..1023
            int m = v >> 3, q = v & 7;
            int gr = row0 + m;
            const float* xsrc = (gr < n) ? &x[(size_t)gr * FDIM + kk + q * 4] : x;
            cp16(&xs[(buf * 128 + m) * GST + q * 4], xsrc, (gr < n) ? 16 : 0);
            cp16(&ws[(buf * 128 + m) * GST + q * 4], &W[(size_t)m * FDIM + kk + q * 4], 16);
        }
        asm volatile("cp.async.commit_group;");
    };

    load_chunk(0);
    for (int c = 0; c < 4; c++) {
        if (c < 3) {
            load_chunk(c + 1);
            asm volatile("cp.async.wait_group 1;");
        } else {
            asm volatile("cp.async.wait_group 0;");
        }
        __syncthreads();

        const float* xb = xs + (c & 1) * 128 * GST;
        const float* wb = ws + (c & 1) * 128 * GST;
        #pragma unroll
        for (int ks = 0; ks < 4; ks++) {
            int k0 = ks * 8;
            unsigned a[2][4];
            #pragma unroll
            for (int mf = 0; mf < 2; mf++) {
                int r = mbase + mf * 16 + gid;
                a[mf][0] = f2tf(xb[r * GST + k0 + tig]);
                a[mf][1] = f2tf(xb[(r + 8) * GST + k0 + tig]);
                a[mf][2] = f2tf(xb[r * GST + k0 + tig + 4]);
                a[mf][3] = f2tf(xb[(r + 8) * GST + k0 + tig + 4]);
            }
            #pragma unroll
            for (int nf = 0; nf < 8; nf++) {
                int cc = nbase + nf * 8 + gid;
                unsigned b0 = f2tf(wb[cc * GST + k0 + tig]);
                unsigned b1 = f2tf(wb[cc * GST + k0 + tig + 4]);
                #pragma unroll
                for (int mf = 0; mf < 2; mf++) {
                    asm volatile(
                        "mma.sync.aligned.m16n8k8.row.col.f32.tf32.tf32.f32 "
                        "{%0,%1,%2,%3}, {%4,%5,%6,%7}, {%8,%9}, {%0,%1,%2,%3};"
                        : "+f"(acc[mf][nf][0]), "+f"(acc[mf][nf][1]),
                          "+f"(acc[mf][nf][2]), "+f"(acc[mf][nf][3])
                        : "r"(a[mf][0]), "r"(a[mf][1]), "r"(a[mf][2]), "r"(a[mf][3]),
                          "r"(b0), "r"(b1));
                }
            }
        }
        __syncthreads();
    }

    // fused attention logits (from fp32 accumulators — full precision)
    float ps[2][2][2], pd[2][2][2];
    #pragma unroll
    for (int i = 0; i < 8; i++) { (&ps[0][0][0])[i] = 0.f; (&pd[0][0][0])[i] = 0.f; }

    #pragma unroll
    for (int nf = 0; nf < 8; nf++) {
        int hh = nf >> 2;
        int head = nw * 2 + hh;
        int cl = (nf & 3) * 8 + tig * 2;
        float as0 = att_src[head * 32 + cl], as1 = att_src[head * 32 + cl + 1];
        float ad0 = att_dst[head * 32 + cl], ad1 = att_dst[head * 32 + cl + 1];
        #pragma unroll
        for (int mf = 0; mf < 2; mf++) {
            ps[mf][0][hh] += acc[mf][nf][0] * as0 + acc[mf][nf][1] * as1;
            ps[mf][1][hh] += acc[mf][nf][2] * as0 + acc[mf][nf][3] * as1;
            pd[mf][0][hh] += acc[mf][nf][0] * ad0 + acc[mf][nf][1] * ad1;
            pd[mf][1][hh] += acc[mf][nf][2] * ad0 + acc[mf][nf][3] * ad1;
        }
    }
    #pragma unroll
    for (int i = 0; i < 8; i++) {
        float* pp = &ps[0][0][0];
        float* qq = &pd[0][0][0];
        pp[i] += __shfl_xor_sync(0xffffffffu, pp[i], 1);
        pp[i] += __shfl_xor_sync(0xffffffffu, pp[i], 2);
        qq[i] += __shfl_xor_sync(0xffffffffu, qq[i], 1);
        qq[i] += __shfl_xor_sync(0xffffffffu, qq[i], 2);
    }
    if (tig == 0) {
        #pragma unroll
        for (int mf = 0; mf < 2; mf++)
            #pragma unroll
            for (int rh = 0; rh < 2; rh++) {
                int r = row0 + mbase + mf * 16 + rh * 8 + gid;
                if (r < n) {
                    #pragma unroll
                    for (int hh = 0; hh < 2; hh++) {
                        g_asrc[r * NHEADS + nw * 2 + hh] = ps[mf][rh][hh];
                        g_adst[r * NHEADS + nw * 2 + hh] = pd[mf][rh][hh];
                    }
                }
            }
    }
    // store h as fp16
    #pragma unroll
    for (int mf = 0; mf < 2; mf++) {
        int r = row0 + mbase + mf * 16 + gid;
        #pragma unroll
        for (int nf = 0; nf < 8; nf++) {
            int c = nbase + nf * 8 + tig * 2;
            if (r < n)
                *(half2*)&g_h[(size_t)r * FDIM + c] = __floats2half2_rn(acc[mf][nf][0], acc[mf][nf][1]);
            if (r + 8 < n)
                *(half2*)&g_h[(size_t)(r + 8) * FDIM + c] = __floats2half2_rn(acc[mf][nf][2], acc[mf][nf][3]);
        }
    }
}

// ---------------- CSR build ----------------
__global__ void k_hist(const void* __restrict__ ei, int E) {
    int e = blockIdx.x * blockDim.x + threadIdx.x;
    if (e >= E) return;
    int dst;
    if (g_idx64) dst = (int)((const long long*)ei)[(size_t)E + e];
    else         dst = ((const int*)ei)[(size_t)E + e];
    atomicAdd(&g_deg[dst], 1);
}

__global__ void k_scan_blk(int n) {
    __shared__ int sh[256];
    int i = blockIdx.x * 256 + threadIdx.x;
    int v = (i < n) ? g_deg[i] : 0;
    sh[threadIdx.x] = v;
    __syncthreads();
    #pragma unroll
    for (int ofs = 1; ofs < 256; ofs <<= 1) {
        int t = (threadIdx.x >= ofs) ? sh[threadIdx.x - ofs] : 0;
        __syncthreads();
        sh[threadIdx.x] += t;
        __syncthreads();
    }
    if (i < n) g_off[i + 1] = sh[threadIdx.x];
    if (threadIdx.x == 255) g_bsum[blockIdx.x] = sh[255];
}

__global__ void k_scan_add(int n, int nb) {
    __shared__ int sh[256];
    int t = threadIdx.x;
    int v = (t < nb) ? g_bsum[t] : 0;
    sh[t] = v;
    __syncthreads();
    #pragma unroll
    for (int ofs = 1; ofs < 256; ofs <<= 1) {
        int x = (t >= ofs) ? sh[t - ofs] : 0;
        __syncthreads();
        sh[t] += x;
        __syncthreads();
    }
    int add = (blockIdx.x > 0) ? sh[blockIdx.x - 1] : 0;
    int i = blockIdx.x * 256 + t;
    if (i >= n) return;
    int incl = g_off[i + 1] + add;
    g_off[i + 1] = incl;
    g_cur[i] = incl - g_deg[i];
    if (i == 0) g_off[0] = 0;
}

__global__ void k_scatter(const void* __restrict__ ei, int E) {
    int e = blockIdx.x * blockDim.x + threadIdx.x;
    if (e >= E) return;
    int src, dst;
    load_edge(ei, e, E, src, dst);
    int pos = atomicAdd(&g_cur[dst], 1);
    g_sedge[pos] = ((unsigned long long)(unsigned)e << 32) | (unsigned)src;
}

// ---------------- aggregate: warp per dst, pipelined gather, no output atomics ----------------
__global__ __launch_bounds__(256) void k_agg(float* __restrict__ out,
                                             float* __restrict__ apool,
                                             const float* __restrict__ bias,
                                             int n) {
    int dst = blockIdx.x * 8 + (threadIdx.x >> 5);
    int lane = threadIdx.x & 31;
    if (dst >= n) return;
    int off0 = g_off[dst];
    int deg = g_off[dst + 1] - off0;

    float4 adst = *(const float4*)&g_adst[dst * NHEADS];

    // pass A: exp + per-head sums (strided)
    float4 s = make_float4(0.f, 0.f, 0.f, 0.f);
    for (int j = lane; j < deg; j += 32) {
        unsigned long long se = g_sedge[off0 + j];
        int src = (int)(unsigned)se;
        float4 a = *(const float4*)&g_asrc[src * NHEADS];
        float4 ex;
        ex.x = lrelu_exp(a.x + adst.x);
        ex.y = lrelu_exp(a.y + adst.y);
        ex.z = lrelu_exp(a.z + adst.z);
        ex.w = lrelu_exp(a.w + adst.w);
        *(float4*)&g_exs[(size_t)(off0 + j) * NHEADS] = ex;
        s.x += ex.x; s.y += ex.y; s.z += ex.z; s.w += ex.w;
    }
    #pragma unroll
    for (int o = 16; o > 0; o >>= 1) {
        s.x += __shfl_xor_sync(0xffffffffu, s.x, o);
        s.y += __shfl_xor_sync(0xffffffffu, s.y, o);
        s.z += __shfl_xor_sync(0xffffffffu, s.z, o);
        s.w += __shfl_xor_sync(0xffffffffu, s.w, o);
    }
    float4 rs;
    rs.x = 1.0f / (s.x + GAT_EPS);
    rs.y = 1.0f / (s.y + GAT_EPS);
    rs.z = 1.0f / (s.z + GAT_EPS);
    rs.w = 1.0f / (s.w + GAT_EPS);

    // pass A2: apool (strided)
    for (int j = lane; j < deg; j += 32) {
        float4 ex = *(const float4*)&g_exs[(size_t)(off0 + j) * NHEADS];
        int e = (int)(g_sedge[off0 + j] >> 32);
        apool[e] = 0.25f * (ex.x * rs.x + ex.y * rs.y + ex.z * rs.z + ex.w * rs.w);
    }

    // pass B: 4-edge pipelined accumulation (MLP=4 on the h gather)
    int head = lane >> 3;
    float rs_h = (head & 2) ? ((head & 1) ? rs.w : rs.z)
                            : ((head & 1) ? rs.y : rs.x);
    float4 acc = make_float4(0.f, 0.f, 0.f, 0.f);
    const __half* hb = g_h;
    int j = 0;
    for (; j + 4 <= deg; j += 4) {
        size_t q = (size_t)(off0 + j);
        unsigned long long se0 = g_sedge[q];
        unsigned long long se1 = g_sedge[q + 1];
        unsigned long long se2 = g_sedge[q + 2];
        unsigned long long se3 = g_sedge[q + 3];
        float e0 = g_exs[q * NHEADS + head];
        float e1 = g_exs[(q + 1) * NHEADS + head];
        float e2 = g_exs[(q + 2) * NHEADS + head];
        float e3 = g_exs[(q + 3) * NHEADS + head];
        uint2 r0 = *(const uint2*)&hb[(size_t)(unsigned)se0 * FDIM + lane * 4];
        uint2 r1 = *(const uint2*)&hb[(size_t)(unsigned)se1 * FDIM + lane * 4];
        uint2 r2 = *(const uint2*)&hb[(size_t)(unsigned)se2 * FDIM + lane * 4];
        uint2 r3 = *(const uint2*)&hb[(size_t)(unsigned)se3 * FDIM + lane * 4];
        float c0 = e0 * rs_h, c1 = e1 * rs_h, c2 = e2 * rs_h, c3 = e3 * rs_h;
        float2 a01, a23;
        a01 = __half22float2(*(const half2*)&r0.x); a23 = __half22float2(*(const half2*)&r0.y);
        acc.x = fmaf(c0, a01.x, acc.x); acc.y = fmaf(c0, a01.y, acc.y);
        acc.z = fmaf(c0, a23.x, acc.z); acc.w = fmaf(c0, a23.y, acc.w);
        a01 = __half22float2(*(const half2*)&r1.x); a23 = __half22float2(*(const half2*)&r1.y);
        acc.x = fmaf(c1, a01.x, acc.x); acc.y = fmaf(c1, a01.y, acc.y);
        acc.z = fmaf(c1, a23.x, acc.z); acc.w = fmaf(c1, a23.y, acc.w);
        a01 = __half22float2(*(const half2*)&r2.x); a23 = __half22float2(*(const half2*)&r2.y);
        acc.x = fmaf(c2, a01.x, acc.x); acc.y = fmaf(c2, a01.y, acc.y);
        acc.z = fmaf(c2, a23.x, acc.z); acc.w = fmaf(c2, a23.y, acc.w);
        a01 = __half22float2(*(const half2*)&r3.x); a23 = __half22float2(*(const half2*)&r3.y);
        acc.x = fmaf(c3, a01.x, acc.x); acc.y = fmaf(c3, a01.y, acc.y);
        acc.z = fmaf(c3, a23.x, acc.z); acc.w = fmaf(c3, a23.y, acc.w);
    }
    for (; j < deg; j++) {
        size_t q = (size_t)(off0 + j);
        unsigned long long se = g_sedge[q];
        float c = g_exs[q * NHEADS + head] * rs_h;
        uint2 r = *(const uint2*)&hb[(size_t)(unsigned)se * FDIM + lane * 4];
        float2 a01 = __half22float2(*(const half2*)&r.x);
        float2 a23 = __half22float2(*(const half2*)&r.y);
        acc.x = fmaf(c, a01.x, acc.x); acc.y = fmaf(c, a01.y, acc.y);
        acc.z = fmaf(c, a23.x, acc.z); acc.w = fmaf(c, a23.y, acc.w);
    }
    float4 bv = *(const float4*)&bias[lane * 4];
    acc.x += bv.x; acc.y += bv.y; acc.z += bv.z; acc.w += bv.w;
    *(float4*)&out[(size_t)dst * FDIM + lane * 4] = acc;

    // reset degree counter for the next graph replay
    if (lane == 0) g_deg[dst] = 0;
}

extern "C" void kernel_launch(void* const* d_in, const int* in_sizes, int n_in,
                              void* d_out, int out_size) {
    const float* x       = (const float*)d_in[0];
    const void*  ei      = d_in[1];
    const float* W       = (const float*)d_in[2];
    const float* att_src = (const float*)d_in[3];
    const float* att_dst = (const float*)d_in[4];
    const float* bias    = (const float*)d_in[5];

    int n = in_sizes[0] / FDIM;
    int E = in_sizes[1] / 2;

    float* out   = (float*)d_out;
    float* apool = out + (size_t)n * FDIM;

    int nb = (n + 255) / 256;

    static int smem_set = 0;
    if (!smem_set) {
        cudaFuncSetAttribute(k_gemm_att, cudaFuncAttributeMaxDynamicSharedMemorySize, GEMM_SMEM);
        smem_set = 1;
    }

    k_gemm_att<<<(n + 127) / 128, 256, GEMM_SMEM>>>(x, W, att_src, att_dst,
                                                    (const unsigned*)ei, n);
    k_hist<<<(E + 255) / 256, 256>>>(ei, E);
    k_scan_blk<<<nb, 256>>>(n);
    k_scan_add<<<nb, 256>>>(n, nb);
    k_scatter<<<(E + 255) / 256, 256>>>(ei, E);
    k_agg<<<(n + 7) / 8, 256>>>(out, apool, bias, n);
}